// round 1
// baseline (speedup 1.0000x reference)
#include <cuda_runtime.h>
#include <math.h>

#define NB   2
#define NS   4096
#define NE   2560
#define NH   8
#define NKV  4
#define ND   256
#define NWIN 1024

// ---------------- scratch (device globals: allocation-free) ----------------
static __device__ float g_qkv[(size_t)NB * NS * (NH + 2 * NKV) * ND]; // [8192, 4096]
static __device__ float g_q  [(size_t)NB * NH  * NS * ND];            // [b,h,s,d]
static __device__ float g_k  [(size_t)NB * NKV * NS * ND];            // [b,kh,s,d]
static __device__ float g_v  [(size_t)NB * NKV * NS * ND];
static __device__ float g_att[(size_t)NB * NS * NH * ND];             // [b,s,h*d]

// ---------------------------------------------------------------------------
// GEMM: C[M,N] = A[M,K] @ B[N,K]^T   (both row-major, K contiguous)
// 128x128 tile, BK=16, 256 threads, 8x8 micro-tile with 16-interleave mapping
// ---------------------------------------------------------------------------
__global__ __launch_bounds__(256) void sgemm_nt(const float* __restrict__ A,
                                                const float* __restrict__ Bm,
                                                float* __restrict__ C,
                                                int M, int N, int K)
{
    __shared__ float As[16][129];
    __shared__ float Bs[16][129];

    int tid = threadIdx.x;
    int tx = tid & 15;
    int ty = tid >> 4;

    const float* Ab = A  + (size_t)blockIdx.y * 128 * K;
    const float* Bb = Bm + (size_t)blockIdx.x * 128 * K;

    float acc[8][8];
#pragma unroll
    for (int i = 0; i < 8; i++)
#pragma unroll
        for (int j = 0; j < 8; j++) acc[i][j] = 0.0f;

    int lr = tid >> 2;        // 0..63
    int lk = (tid & 3) * 4;   // 0,4,8,12

    for (int k0 = 0; k0 < K; k0 += 16) {
#pragma unroll
        for (int r = 0; r < 2; r++) {
            int row = lr + r * 64;
            float4 va = *(const float4*)(Ab + (size_t)row * K + k0 + lk);
            As[lk + 0][row] = va.x; As[lk + 1][row] = va.y;
            As[lk + 2][row] = va.z; As[lk + 3][row] = va.w;
            float4 vb = *(const float4*)(Bb + (size_t)row * K + k0 + lk);
            Bs[lk + 0][row] = vb.x; Bs[lk + 1][row] = vb.y;
            Bs[lk + 2][row] = vb.z; Bs[lk + 3][row] = vb.w;
        }
        __syncthreads();

#pragma unroll
        for (int kk = 0; kk < 16; kk++) {
            float a[8], b[8];
#pragma unroll
            for (int i = 0; i < 8; i++) a[i] = As[kk][ty + i * 16];
#pragma unroll
            for (int j = 0; j < 8; j++) b[j] = Bs[kk][tx + j * 16];
#pragma unroll
            for (int i = 0; i < 8; i++)
#pragma unroll
                for (int j = 0; j < 8; j++) acc[i][j] += a[i] * b[j];
        }
        __syncthreads();
    }

#pragma unroll
    for (int i = 0; i < 8; i++) {
        size_t row = (size_t)blockIdx.y * 128 + ty + i * 16;
#pragma unroll
        for (int j = 0; j < 8; j++) {
            C[row * N + blockIdx.x * 128 + tx + j * 16] = acc[i][j];
        }
    }
}

// ---------------------------------------------------------------------------
// RMSNorm + RoPE + scatter into q/k/v buffers.
// One block per token (512 thr = 16 warps): warp w handles head-slot w.
//   warps 0..7  -> q heads (norm + rope + *SCALING) -> g_q[b,h,s,:]
//   warps 8..11 -> k heads (norm + rope)            -> g_k[b,kh,idx[s],:]
//   warps 12..15-> v heads (copy)                   -> g_v[b,kh,idx[s],:]
// ---------------------------------------------------------------------------
__global__ __launch_bounds__(512) void norm_rope_kernel(
        const float* __restrict__ fcos, const float* __restrict__ fsin,
        const int*   __restrict__ kvidx,
        const float* __restrict__ qw, const float* __restrict__ kw)
{
    int token = blockIdx.x;
    int b = token / NS;
    int s = token - b * NS;
    int warp = threadIdx.x >> 5;
    int lane = threadIdx.x & 31;

    const float* src = g_qkv + (size_t)token * ((NH + 2 * NKV) * ND) + warp * ND;

    float x1[4], x2[4];
#pragma unroll
    for (int i = 0; i < 4; i++) {
        x1[i] = src[lane + 32 * i];
        x2[i] = src[128 + lane + 32 * i];
    }

    if (warp >= 12) { // V: raw copy
        int kh = warp - 12;
        float* dst = g_v + ((size_t)(b * NKV + kh) * NS + kvidx[s]) * ND;
#pragma unroll
        for (int i = 0; i < 4; i++) {
            dst[lane + 32 * i]       = x1[i];
            dst[128 + lane + 32 * i] = x2[i];
        }
        return;
    }

    float ss = 0.0f;
#pragma unroll
    for (int i = 0; i < 4; i++) ss += x1[i] * x1[i] + x2[i] * x2[i];
#pragma unroll
    for (int m = 16; m; m >>= 1) ss += __shfl_xor_sync(0xffffffffu, ss, m);
    float inv = rsqrtf(ss * (1.0f / ND) + 1e-6f);

    const float* w   = (warp < 8) ? qw : kw;
    float scale      = (warp < 8) ? 0.0625f : 1.0f; // SCALING = 256^-0.5 folded into q
    float* dst;
    if (warp < 8) dst = g_q + ((size_t)(b * NH + warp) * NS + s) * ND;
    else          dst = g_k + ((size_t)(b * NKV + (warp - 8)) * NS + kvidx[s]) * ND;

#pragma unroll
    for (int i = 0; i < 4; i++) {
        int d = lane + 32 * i;
        float c  = fcos[(size_t)s * 128 + d];
        float sn = fsin[(size_t)s * 128 + d];
        float y1 = x1[i] * inv * (1.0f + w[d]);
        float y2 = x2[i] * inv * (1.0f + w[d + 128]);
        dst[d]       = (y1 * c - y2 * sn) * scale;
        dst[d + 128] = (y2 * c + y1 * sn) * scale;
    }
}

// ---------------------------------------------------------------------------
// Sliding-window flash attention, fp32. BM=BN=64, D=256, 256 threads.
// Thread (tx,ty): q rows {ty+16i}, score cols {tx+16j}, out d-cols {tx+16c}.
// ---------------------------------------------------------------------------
#define ST 257  // padded row stride for Q/K/V tiles
#define PST 65  // padded row stride for P tile

__global__ __launch_bounds__(256) void attn_kernel()
{
    extern __shared__ float sm[];
    float* Qs = sm;
    float* Ks = Qs + 64 * ST;
    float* Vs = Ks + 64 * ST;
    float* Ps = Vs + 64 * ST;

    int qt = blockIdx.x, h = blockIdx.y, b = blockIdx.z;
    int q0 = qt * 64;
    int kh = h >> 1; // H/HKV = 2

    const float* Qg = g_q + ((size_t)(b * NH + h) * NS + q0) * ND;
    const float* Kg = g_k + (size_t)(b * NKV + kh) * NS * ND;
    const float* Vg = g_v + (size_t)(b * NKV + kh) * NS * ND;

    int tid = threadIdx.x;
    int tx = tid & 15;
    int ty = tid >> 4;

    // load Q tile (64 x 256)
    for (int i = tid; i < 64 * 64; i += 256) {
        int r = i >> 6, v = (i & 63) << 2;
        float4 q4 = *(const float4*)(Qg + (size_t)r * ND + v);
        float* d = Qs + r * ST + v;
        d[0] = q4.x; d[1] = q4.y; d[2] = q4.z; d[3] = q4.w;
    }

    float m[4], l[4], acc[4][16];
#pragma unroll
    for (int i = 0; i < 4; i++) {
        m[i] = -1e30f; l[i] = 0.0f;
#pragma unroll
        for (int c = 0; c < 16; c++) acc[i][c] = 0.0f;
    }

    int t0 = qt - 16; if (t0 < 0) t0 = 0; // WINDOW/64 = 16

    for (int kt = t0; kt <= qt; kt++) {
        int k0 = kt * 64;
        __syncthreads(); // previous iter's K/V/P reads complete
        for (int i = tid; i < 64 * 64; i += 256) {
            int r = i >> 6, v = (i & 63) << 2;
            float4 k4 = *(const float4*)(Kg + (size_t)(k0 + r) * ND + v);
            float* dk = Ks + r * ST + v;
            dk[0] = k4.x; dk[1] = k4.y; dk[2] = k4.z; dk[3] = k4.w;
            float4 v4 = *(const float4*)(Vg + (size_t)(k0 + r) * ND + v);
            float* dv = Vs + r * ST + v;
            dv[0] = v4.x; dv[1] = v4.y; dv[2] = v4.z; dv[3] = v4.w;
        }
        __syncthreads();

        // scores S = Q @ K^T (q pre-scaled)
        float sc[4][4];
#pragma unroll
        for (int i = 0; i < 4; i++)
#pragma unroll
            for (int j = 0; j < 4; j++) sc[i][j] = 0.0f;

        for (int kk = 0; kk < ND; kk++) {
            float qa[4], kb[4];
#pragma unroll
            for (int i = 0; i < 4; i++) qa[i] = Qs[(ty + i * 16) * ST + kk];
#pragma unroll
            for (int j = 0; j < 4; j++) kb[j] = Ks[(tx + j * 16) * ST + kk];
#pragma unroll
            for (int i = 0; i < 4; i++)
#pragma unroll
                for (int j = 0; j < 4; j++) sc[i][j] += qa[i] * kb[j];
        }

        // softcap + mask + online softmax update
#pragma unroll
        for (int i = 0; i < 4; i++) {
            int qi = q0 + ty + i * 16;
            float mx = -1e30f;
#pragma unroll
            for (int j = 0; j < 4; j++) {
                int kj = k0 + tx + j * 16;
                float v = tanhf(sc[i][j] * 0.02f) * 50.0f;
                bool ok = (kj <= qi) && (qi - kj < NWIN);
                v = ok ? v : -1e30f;
                sc[i][j] = v;
                mx = fmaxf(mx, v);
            }
#pragma unroll
            for (int sft = 8; sft; sft >>= 1)
                mx = fmaxf(mx, __shfl_xor_sync(0xffffffffu, mx, sft));

            float mn = fmaxf(m[i], mx);
            float corr = __expf(m[i] - mn);
            m[i] = mn;
            l[i] *= corr;
            float rs = 0.0f;
#pragma unroll
            for (int j = 0; j < 4; j++) {
                float p = __expf(sc[i][j] - mn);
                sc[i][j] = p;
                rs += p;
            }
#pragma unroll
            for (int sft = 8; sft; sft >>= 1)
                rs += __shfl_xor_sync(0xffffffffu, rs, sft);
            l[i] += rs;
#pragma unroll
            for (int c = 0; c < 16; c++) acc[i][c] *= corr;
#pragma unroll
            for (int j = 0; j < 4; j++)
                Ps[(ty + i * 16) * PST + tx + j * 16] = sc[i][j];
        }
        __syncthreads();

        // O += P @ V
        for (int kk = 0; kk < 64; kk++) {
            float p[4];
#pragma unroll
            for (int i = 0; i < 4; i++) p[i] = Ps[(ty + i * 16) * PST + kk];
#pragma unroll
            for (int c = 0; c < 16; c++) {
                float vv = Vs[kk * ST + tx + c * 16];
#pragma unroll
                for (int i = 0; i < 4; i++) acc[i][c] += p[i] * vv;
            }
        }
    }

    // epilogue: divide by l, write [b, s, h*D + d]
    float* Og = g_att + ((size_t)b * NS + q0) * (NH * ND) + h * ND;
#pragma unroll
    for (int i = 0; i < 4; i++) {
        float invl = 1.0f / l[i];
        int r = ty + i * 16;
#pragma unroll
        for (int c = 0; c < 16; c++) {
            Og[(size_t)r * (NH * ND) + tx + c * 16] = acc[i][c] * invl;
        }
    }
}

// ---------------------------------------------------------------------------
extern "C" void kernel_launch(void* const* d_in, const int* in_sizes, int n_in,
                              void* d_out, int out_size)
{
    const float* hidden = (const float*)d_in[0];
    const float* fcos   = (const float*)d_in[1];
    const float* fsin   = (const float*)d_in[2];
    const int*   kvidx  = (const int*)  d_in[3];
    // d_in[4] k_cache, d_in[5] v_cache: fully overwritten -> unused
    // d_in[6] mask, d_in[7] local_mask: analytic sliding-causal mask -> unused
    const float* w_qkv  = (const float*)d_in[8];
    const float* w_o    = (const float*)d_in[9];
    const float* qnw    = (const float*)d_in[10];
    const float* knw    = (const float*)d_in[11];
    float* out = (float*)d_out;

    void* p;
    cudaGetSymbolAddress(&p, g_qkv); float* qkv_ptr = (float*)p;
    cudaGetSymbolAddress(&p, g_att); float* att_ptr = (float*)p;

    // 1) QKV projection: [8192,2560] x [4096,2560]^T
    {
        dim3 grid((NH + 2 * NKV) * ND / 128, NB * NS / 128);
        sgemm_nt<<<grid, 256>>>(hidden, w_qkv, qkv_ptr,
                                NB * NS, (NH + 2 * NKV) * ND, NE);
    }

    // 2) RMSNorm + RoPE + cache scatter
    norm_rope_kernel<<<NB * NS, 512>>>(fcos, fsin, kvidx, qnw, knw);

    // 3) sliding-window flash attention
    {
        size_t smem = (size_t)(3 * 64 * ST + 64 * PST) * sizeof(float);
        cudaFuncSetAttribute(attn_kernel,
                             cudaFuncAttributeMaxDynamicSharedMemorySize,
                             (int)smem);
        dim3 grid(NS / 64, NH, NB);
        attn_kernel<<<grid, 256, smem>>>();
    }

    // 4) output projection: [8192,2048] x [2560,2048]^T
    {
        dim3 grid(NE / 128, NB * NS / 128);
        sgemm_nt<<<grid, 256>>>(att_ptr, w_o, out, NB * NS, NE, NH * ND);
    }
}

// round 2
// speedup vs baseline: 1.9326x; 1.9326x over previous
#include <cuda_runtime.h>
#include <math.h>

#define NB   2
#define NS   4096
#define NE   2560
#define NH   8
#define NKV  4
#define ND   256
#define NWIN 1024

// ---------------- scratch (device globals: allocation-free) ----------------
static __device__ float g_qkv[(size_t)NB * NS * (NH + 2 * NKV) * ND]; // [8192, 4096]
static __device__ float g_q  [(size_t)NB * NH  * NS * ND];            // [b,h,s,d]
static __device__ float g_k  [(size_t)NB * NKV * NS * ND];            // [b,kh,s,d]
static __device__ float g_v  [(size_t)NB * NKV * NS * ND];
static __device__ float g_att[(size_t)NB * NS * NH * ND];             // [b,s,h*d]

// ---------------------------------------------------------------------------
// TF32 tensor-core GEMM: C[M,N] = A[M,K] @ B[N,K]^T  (row-major, K contiguous)
// 128x128 block tile, BK=32, 256 threads (8 warps, each 64x32),
// mma.sync m16n8k8 tf32, smem pitch 36 floats (conflict-free frag loads),
// register-prefetch double buffering of gmem loads.
// ---------------------------------------------------------------------------
#define SPITCH 36

__device__ __forceinline__ unsigned f2tf32(float f) {
    unsigned u;
    asm volatile("cvt.rna.tf32.f32 %0, %1;" : "=r"(u) : "f"(f));
    return u;
}

__global__ __launch_bounds__(256, 1) void tf32gemm_nt(
        const float* __restrict__ A, const float* __restrict__ Bm,
        float* __restrict__ C, int M, int N, int K)
{
    __shared__ unsigned As[128 * SPITCH];
    __shared__ unsigned Bs[128 * SPITCH];

    int tid  = threadIdx.x;
    int lane = tid & 31;
    int warp = tid >> 5;
    int wm = (warp & 1) * 64;   // warp m offset in tile
    int wn = (warp >> 1) * 32;  // warp n offset in tile

    const float* Ab = A  + (size_t)blockIdx.y * 128 * K;
    const float* Bb = Bm + (size_t)blockIdx.x * 128 * K;

    int lr = tid >> 3;        // 0..31  (row within 32-row group)
    int lc = (tid & 7) * 4;   // 0,4,...,28 (k col)

    float4 pa[4], pb[4];
#pragma unroll
    for (int r = 0; r < 4; r++) {
        pa[r] = *(const float4*)(Ab + (size_t)(lr + r * 32) * K + lc);
        pb[r] = *(const float4*)(Bb + (size_t)(lr + r * 32) * K + lc);
    }

    float acc[16][4];
#pragma unroll
    for (int t = 0; t < 16; t++)
#pragma unroll
        for (int e = 0; e < 4; e++) acc[t][e] = 0.0f;

    int fr = lane >> 2;  // fragment row  0..7
    int fc = lane & 3;   // fragment kcol 0..3

    for (int k0 = 0; k0 < K; k0 += 32) {
        // commit prefetched chunk to smem (converted to tf32)
#pragma unroll
        for (int r = 0; r < 4; r++) {
            uint4 ua, ub;
            ua.x = f2tf32(pa[r].x); ua.y = f2tf32(pa[r].y);
            ua.z = f2tf32(pa[r].z); ua.w = f2tf32(pa[r].w);
            ub.x = f2tf32(pb[r].x); ub.y = f2tf32(pb[r].y);
            ub.z = f2tf32(pb[r].z); ub.w = f2tf32(pb[r].w);
            *(uint4*)&As[(lr + r * 32) * SPITCH + lc] = ua;
            *(uint4*)&Bs[(lr + r * 32) * SPITCH + lc] = ub;
        }
        __syncthreads();

        if (k0 + 32 < K) {
#pragma unroll
            for (int r = 0; r < 4; r++) {
                pa[r] = *(const float4*)(Ab + (size_t)(lr + r * 32) * K + k0 + 32 + lc);
                pb[r] = *(const float4*)(Bb + (size_t)(lr + r * 32) * K + k0 + 32 + lc);
            }
        }

#pragma unroll
        for (int ks = 0; ks < 4; ks++) {
            int kb = ks * 8;
            unsigned af[4][4], bf[4][2];
#pragma unroll
            for (int i = 0; i < 4; i++) {
                int m = wm + i * 16 + fr;
                af[i][0] = As[m * SPITCH + kb + fc];
                af[i][1] = As[(m + 8) * SPITCH + kb + fc];
                af[i][2] = As[m * SPITCH + kb + fc + 4];
                af[i][3] = As[(m + 8) * SPITCH + kb + fc + 4];
            }
#pragma unroll
            for (int j = 0; j < 4; j++) {
                int n = wn + j * 8 + fr;
                bf[j][0] = Bs[n * SPITCH + kb + fc];
                bf[j][1] = Bs[n * SPITCH + kb + fc + 4];
            }
#pragma unroll
            for (int i = 0; i < 4; i++)
#pragma unroll
                for (int j = 0; j < 4; j++) {
                    float* d = acc[i * 4 + j];
                    asm volatile(
                        "mma.sync.aligned.m16n8k8.row.col.f32.tf32.tf32.f32 "
                        "{%0,%1,%2,%3},{%4,%5,%6,%7},{%8,%9},{%0,%1,%2,%3};"
                        : "+f"(d[0]), "+f"(d[1]), "+f"(d[2]), "+f"(d[3])
                        : "r"(af[i][0]), "r"(af[i][1]), "r"(af[i][2]), "r"(af[i][3]),
                          "r"(bf[j][0]), "r"(bf[j][1]));
                }
        }
        __syncthreads();
    }

    // epilogue: d0:(r,2c) d1:(r,2c+1) d2:(r+8,2c) d3:(r+8,2c+1)
    int c2 = (lane & 3) * 2;
#pragma unroll
    for (int i = 0; i < 4; i++) {
        size_t row0 = (size_t)blockIdx.y * 128 + wm + i * 16 + fr;
#pragma unroll
        for (int j = 0; j < 4; j++) {
            float* d = acc[i * 4 + j];
            size_t col = (size_t)blockIdx.x * 128 + wn + j * 8 + c2;
            *(float2*)&C[row0 * N + col]       = make_float2(d[0], d[1]);
            *(float2*)&C[(row0 + 8) * N + col] = make_float2(d[2], d[3]);
        }
    }
}

// ---------------------------------------------------------------------------
// RMSNorm + RoPE + scatter into q/k/v buffers.
// ---------------------------------------------------------------------------
__global__ __launch_bounds__(512) void norm_rope_kernel(
        const float* __restrict__ fcos, const float* __restrict__ fsin,
        const int*   __restrict__ kvidx,
        const float* __restrict__ qw, const float* __restrict__ kw)
{
    int token = blockIdx.x;
    int b = token / NS;
    int s = token - b * NS;
    int warp = threadIdx.x >> 5;
    int lane = threadIdx.x & 31;

    const float* src = g_qkv + (size_t)token * ((NH + 2 * NKV) * ND) + warp * ND;

    float x1[4], x2[4];
#pragma unroll
    for (int i = 0; i < 4; i++) {
        x1[i] = src[lane + 32 * i];
        x2[i] = src[128 + lane + 32 * i];
    }

    if (warp >= 12) { // V: raw copy
        int kh = warp - 12;
        float* dst = g_v + ((size_t)(b * NKV + kh) * NS + kvidx[s]) * ND;
#pragma unroll
        for (int i = 0; i < 4; i++) {
            dst[lane + 32 * i]       = x1[i];
            dst[128 + lane + 32 * i] = x2[i];
        }
        return;
    }

    float ss = 0.0f;
#pragma unroll
    for (int i = 0; i < 4; i++) ss += x1[i] * x1[i] + x2[i] * x2[i];
#pragma unroll
    for (int m = 16; m; m >>= 1) ss += __shfl_xor_sync(0xffffffffu, ss, m);
    float inv = rsqrtf(ss * (1.0f / ND) + 1e-6f);

    const float* w   = (warp < 8) ? qw : kw;
    float scale      = (warp < 8) ? 0.0625f : 1.0f; // SCALING folded into q
    float* dst;
    if (warp < 8) dst = g_q + ((size_t)(b * NH + warp) * NS + s) * ND;
    else          dst = g_k + ((size_t)(b * NKV + (warp - 8)) * NS + kvidx[s]) * ND;

#pragma unroll
    for (int i = 0; i < 4; i++) {
        int d = lane + 32 * i;
        float c  = fcos[(size_t)s * 128 + d];
        float sn = fsin[(size_t)s * 128 + d];
        float y1 = x1[i] * inv * (1.0f + w[d]);
        float y2 = x2[i] * inv * (1.0f + w[d + 128]);
        dst[d]       = (y1 * c - y2 * sn) * scale;
        dst[d + 128] = (y2 * c + y1 * sn) * scale;
    }
}

// ---------------------------------------------------------------------------
// Sliding-window flash attention, fp32. BM=BN=64, D=256, 256 threads.
// ---------------------------------------------------------------------------
#define ST 257
#define PST 65

__global__ __launch_bounds__(256) void attn_kernel()
{
    extern __shared__ float sm[];
    float* Qs = sm;
    float* Ks = Qs + 64 * ST;
    float* Vs = Ks + 64 * ST;
    float* Ps = Vs + 64 * ST;

    int qt = blockIdx.x, h = blockIdx.y, b = blockIdx.z;
    int q0 = qt * 64;
    int kh = h >> 1;

    const float* Qg = g_q + ((size_t)(b * NH + h) * NS + q0) * ND;
    const float* Kg = g_k + (size_t)(b * NKV + kh) * NS * ND;
    const float* Vg = g_v + (size_t)(b * NKV + kh) * NS * ND;

    int tid = threadIdx.x;
    int tx = tid & 15;
    int ty = tid >> 4;

    for (int i = tid; i < 64 * 64; i += 256) {
        int r = i >> 6, v = (i & 63) << 2;
        float4 q4 = *(const float4*)(Qg + (size_t)r * ND + v);
        float* d = Qs + r * ST + v;
        d[0] = q4.x; d[1] = q4.y; d[2] = q4.z; d[3] = q4.w;
    }

    float m[4], l[4], acc[4][16];
#pragma unroll
    for (int i = 0; i < 4; i++) {
        m[i] = -1e30f; l[i] = 0.0f;
#pragma unroll
        for (int c = 0; c < 16; c++) acc[i][c] = 0.0f;
    }

    int t0 = qt - 16; if (t0 < 0) t0 = 0;

    for (int kt = t0; kt <= qt; kt++) {
        int k0 = kt * 64;
        __syncthreads();
        for (int i = tid; i < 64 * 64; i += 256) {
            int r = i >> 6, v = (i & 63) << 2;
            float4 k4 = *(const float4*)(Kg + (size_t)(k0 + r) * ND + v);
            float* dk = Ks + r * ST + v;
            dk[0] = k4.x; dk[1] = k4.y; dk[2] = k4.z; dk[3] = k4.w;
            float4 v4 = *(const float4*)(Vg + (size_t)(k0 + r) * ND + v);
            float* dv = Vs + r * ST + v;
            dv[0] = v4.x; dv[1] = v4.y; dv[2] = v4.z; dv[3] = v4.w;
        }
        __syncthreads();

        float sc[4][4];
#pragma unroll
        for (int i = 0; i < 4; i++)
#pragma unroll
            for (int j = 0; j < 4; j++) sc[i][j] = 0.0f;

        for (int kk = 0; kk < ND; kk++) {
            float qa[4], kb[4];
#pragma unroll
            for (int i = 0; i < 4; i++) qa[i] = Qs[(ty + i * 16) * ST + kk];
#pragma unroll
            for (int j = 0; j < 4; j++) kb[j] = Ks[(tx + j * 16) * ST + kk];
#pragma unroll
            for (int i = 0; i < 4; i++)
#pragma unroll
                for (int j = 0; j < 4; j++) sc[i][j] += qa[i] * kb[j];
        }

#pragma unroll
        for (int i = 0; i < 4; i++) {
            int qi = q0 + ty + i * 16;
            float mx = -1e30f;
#pragma unroll
            for (int j = 0; j < 4; j++) {
                int kj = k0 + tx + j * 16;
                float v = tanhf(sc[i][j] * 0.02f) * 50.0f;
                bool ok = (kj <= qi) && (qi - kj < NWIN);
                v = ok ? v : -1e30f;
                sc[i][j] = v;
                mx = fmaxf(mx, v);
            }
#pragma unroll
            for (int sft = 8; sft; sft >>= 1)
                mx = fmaxf(mx, __shfl_xor_sync(0xffffffffu, mx, sft));

            float mn = fmaxf(m[i], mx);
            float corr = __expf(m[i] - mn);
            m[i] = mn;
            l[i] *= corr;
            float rs = 0.0f;
#pragma unroll
            for (int j = 0; j < 4; j++) {
                float p = __expf(sc[i][j] - mn);
                sc[i][j] = p;
                rs += p;
            }
#pragma unroll
            for (int sft = 8; sft; sft >>= 1)
                rs += __shfl_xor_sync(0xffffffffu, rs, sft);
            l[i] += rs;
#pragma unroll
            for (int c = 0; c < 16; c++) acc[i][c] *= corr;
#pragma unroll
            for (int j = 0; j < 4; j++)
                Ps[(ty + i * 16) * PST + tx + j * 16] = sc[i][j];
        }
        __syncthreads();

        for (int kk = 0; kk < 64; kk++) {
            float p[4];
#pragma unroll
            for (int i = 0; i < 4; i++) p[i] = Ps[(ty + i * 16) * PST + kk];
#pragma unroll
            for (int c = 0; c < 16; c++) {
                float vv = Vs[kk * ST + tx + c * 16];
#pragma unroll
                for (int i = 0; i < 4; i++) acc[i][c] += p[i] * vv;
            }
        }
    }

    float* Og = g_att + ((size_t)b * NS + q0) * (NH * ND) + h * ND;
#pragma unroll
    for (int i = 0; i < 4; i++) {
        float invl = 1.0f / l[i];
        int r = ty + i * 16;
#pragma unroll
        for (int c = 0; c < 16; c++) {
            Og[(size_t)r * (NH * ND) + tx + c * 16] = acc[i][c] * invl;
        }
    }
}

// ---------------------------------------------------------------------------
extern "C" void kernel_launch(void* const* d_in, const int* in_sizes, int n_in,
                              void* d_out, int out_size)
{
    const float* hidden = (const float*)d_in[0];
    const float* fcos   = (const float*)d_in[1];
    const float* fsin   = (const float*)d_in[2];
    const int*   kvidx  = (const int*)  d_in[3];
    const float* w_qkv  = (const float*)d_in[8];
    const float* w_o    = (const float*)d_in[9];
    const float* qnw    = (const float*)d_in[10];
    const float* knw    = (const float*)d_in[11];
    float* out = (float*)d_out;

    void* p;
    cudaGetSymbolAddress(&p, g_qkv); float* qkv_ptr = (float*)p;
    cudaGetSymbolAddress(&p, g_att); float* att_ptr = (float*)p;

    // 1) QKV projection: [8192,2560] x [4096,2560]^T  (tf32 tensor cores)
    {
        dim3 grid((NH + 2 * NKV) * ND / 128, NB * NS / 128);
        tf32gemm_nt<<<grid, 256>>>(hidden, w_qkv, qkv_ptr,
                                   NB * NS, (NH + 2 * NKV) * ND, NE);
    }

    // 2) RMSNorm + RoPE + cache scatter
    norm_rope_kernel<<<NB * NS, 512>>>(fcos, fsin, kvidx, qnw, knw);

    // 3) sliding-window flash attention
    {
        size_t smem = (size_t)(3 * 64 * ST + 64 * PST) * sizeof(float);
        cudaFuncSetAttribute(attn_kernel,
                             cudaFuncAttributeMaxDynamicSharedMemorySize,
                             (int)smem);
        dim3 grid(NS / 64, NH, NB);
        attn_kernel<<<grid, 256, smem>>>();
    }

    // 4) output projection: [8192,2048] x [2560,2048]^T (tf32 tensor cores)
    {
        dim3 grid(NE / 128, NB * NS / 128);
        tf32gemm_nt<<<grid, 256>>>(att_ptr, w_o, out, NB * NS, NE, NH * ND);
    }
}

// round 3
// speedup vs baseline: 2.8179x; 1.4581x over previous
#include <cuda_runtime.h>
#include <math.h>

#define NB   2
#define NS   4096
#define NE   2560
#define NH   8
#define NKV  4
#define ND   256
#define NWIN 1024

// ---------------- scratch (device globals: allocation-free) ----------------
static __device__ float g_qkv[(size_t)NB * NS * (NH + 2 * NKV) * ND]; // [8192, 4096]
static __device__ float g_q  [(size_t)NB * NH  * NS * ND];            // [b,h,s,d]
static __device__ float g_k  [(size_t)NB * NKV * NS * ND];            // [b,kh,s,d]
static __device__ float g_v  [(size_t)NB * NKV * NS * ND];
static __device__ float g_att[(size_t)NB * NS * NH * ND];             // [b,s,h*d]

__device__ __forceinline__ unsigned f2tf32(float f) {
    unsigned u;
    asm volatile("cvt.rna.tf32.f32 %0, %1;" : "=r"(u) : "f"(f));
    return u;
}

__device__ __forceinline__ void mma_tf32(float* d,
        unsigned a0, unsigned a1, unsigned a2, unsigned a3,
        unsigned b0, unsigned b1) {
    asm volatile(
        "mma.sync.aligned.m16n8k8.row.col.f32.tf32.tf32.f32 "
        "{%0,%1,%2,%3},{%4,%5,%6,%7},{%8,%9},{%0,%1,%2,%3};"
        : "+f"(d[0]), "+f"(d[1]), "+f"(d[2]), "+f"(d[3])
        : "r"(a0), "r"(a1), "r"(a2), "r"(a3), "r"(b0), "r"(b1));
}

// ---------------------------------------------------------------------------
// TF32 tensor-core GEMM: C[M,N] = A[M,K] @ B[N,K]^T  (row-major, K contiguous)
// ---------------------------------------------------------------------------
#define SPITCH 36

__global__ __launch_bounds__(256, 1) void tf32gemm_nt(
        const float* __restrict__ A, const float* __restrict__ Bm,
        float* __restrict__ C, int M, int N, int K)
{
    __shared__ unsigned As[128 * SPITCH];
    __shared__ unsigned Bs[128 * SPITCH];

    int tid  = threadIdx.x;
    int lane = tid & 31;
    int warp = tid >> 5;
    int wm = (warp & 1) * 64;
    int wn = (warp >> 1) * 32;

    const float* Ab = A  + (size_t)blockIdx.y * 128 * K;
    const float* Bb = Bm + (size_t)blockIdx.x * 128 * K;

    int lr = tid >> 3;
    int lc = (tid & 7) * 4;

    float4 pa[4], pb[4];
#pragma unroll
    for (int r = 0; r < 4; r++) {
        pa[r] = *(const float4*)(Ab + (size_t)(lr + r * 32) * K + lc);
        pb[r] = *(const float4*)(Bb + (size_t)(lr + r * 32) * K + lc);
    }

    float acc[16][4];
#pragma unroll
    for (int t = 0; t < 16; t++)
#pragma unroll
        for (int e = 0; e < 4; e++) acc[t][e] = 0.0f;

    int fr = lane >> 2;
    int fc = lane & 3;

    for (int k0 = 0; k0 < K; k0 += 32) {
#pragma unroll
        for (int r = 0; r < 4; r++) {
            uint4 ua, ub;
            ua.x = f2tf32(pa[r].x); ua.y = f2tf32(pa[r].y);
            ua.z = f2tf32(pa[r].z); ua.w = f2tf32(pa[r].w);
            ub.x = f2tf32(pb[r].x); ub.y = f2tf32(pb[r].y);
            ub.z = f2tf32(pb[r].z); ub.w = f2tf32(pb[r].w);
            *(uint4*)&As[(lr + r * 32) * SPITCH + lc] = ua;
            *(uint4*)&Bs[(lr + r * 32) * SPITCH + lc] = ub;
        }
        __syncthreads();

        if (k0 + 32 < K) {
#pragma unroll
            for (int r = 0; r < 4; r++) {
                pa[r] = *(const float4*)(Ab + (size_t)(lr + r * 32) * K + k0 + 32 + lc);
                pb[r] = *(const float4*)(Bb + (size_t)(lr + r * 32) * K + k0 + 32 + lc);
            }
        }

#pragma unroll
        for (int ks = 0; ks < 4; ks++) {
            int kb = ks * 8;
            unsigned af[4][4], bf[4][2];
#pragma unroll
            for (int i = 0; i < 4; i++) {
                int m = wm + i * 16 + fr;
                af[i][0] = As[m * SPITCH + kb + fc];
                af[i][1] = As[(m + 8) * SPITCH + kb + fc];
                af[i][2] = As[m * SPITCH + kb + fc + 4];
                af[i][3] = As[(m + 8) * SPITCH + kb + fc + 4];
            }
#pragma unroll
            for (int j = 0; j < 4; j++) {
                int n = wn + j * 8 + fr;
                bf[j][0] = Bs[n * SPITCH + kb + fc];
                bf[j][1] = Bs[n * SPITCH + kb + fc + 4];
            }
#pragma unroll
            for (int i = 0; i < 4; i++)
#pragma unroll
                for (int j = 0; j < 4; j++)
                    mma_tf32(acc[i * 4 + j], af[i][0], af[i][1], af[i][2], af[i][3],
                             bf[j][0], bf[j][1]);
        }
        __syncthreads();
    }

    int c2 = (lane & 3) * 2;
#pragma unroll
    for (int i = 0; i < 4; i++) {
        size_t row0 = (size_t)blockIdx.y * 128 + wm + i * 16 + fr;
#pragma unroll
        for (int j = 0; j < 4; j++) {
            float* d = acc[i * 4 + j];
            size_t col = (size_t)blockIdx.x * 128 + wn + j * 8 + c2;
            *(float2*)&C[row0 * N + col]       = make_float2(d[0], d[1]);
            *(float2*)&C[(row0 + 8) * N + col] = make_float2(d[2], d[3]);
        }
    }
}

// ---------------------------------------------------------------------------
// RMSNorm + RoPE + scatter into q/k/v buffers.
// ---------------------------------------------------------------------------
__global__ __launch_bounds__(512) void norm_rope_kernel(
        const float* __restrict__ fcos, const float* __restrict__ fsin,
        const int*   __restrict__ kvidx,
        const float* __restrict__ qw, const float* __restrict__ kw)
{
    int token = blockIdx.x;
    int b = token / NS;
    int s = token - b * NS;
    int warp = threadIdx.x >> 5;
    int lane = threadIdx.x & 31;

    const float* src = g_qkv + (size_t)token * ((NH + 2 * NKV) * ND) + warp * ND;

    float x1[4], x2[4];
#pragma unroll
    for (int i = 0; i < 4; i++) {
        x1[i] = src[lane + 32 * i];
        x2[i] = src[128 + lane + 32 * i];
    }

    if (warp >= 12) { // V: raw copy
        int kh = warp - 12;
        float* dst = g_v + ((size_t)(b * NKV + kh) * NS + kvidx[s]) * ND;
#pragma unroll
        for (int i = 0; i < 4; i++) {
            dst[lane + 32 * i]       = x1[i];
            dst[128 + lane + 32 * i] = x2[i];
        }
        return;
    }

    float ss = 0.0f;
#pragma unroll
    for (int i = 0; i < 4; i++) ss += x1[i] * x1[i] + x2[i] * x2[i];
#pragma unroll
    for (int m = 16; m; m >>= 1) ss += __shfl_xor_sync(0xffffffffu, ss, m);
    float inv = rsqrtf(ss * (1.0f / ND) + 1e-6f);

    const float* w   = (warp < 8) ? qw : kw;
    float scale      = (warp < 8) ? 0.0625f : 1.0f; // SCALING folded into q
    float* dst;
    if (warp < 8) dst = g_q + ((size_t)(b * NH + warp) * NS + s) * ND;
    else          dst = g_k + ((size_t)(b * NKV + (warp - 8)) * NS + kvidx[s]) * ND;

#pragma unroll
    for (int i = 0; i < 4; i++) {
        int d = lane + 32 * i;
        float c  = fcos[(size_t)s * 128 + d];
        float sn = fsin[(size_t)s * 128 + d];
        float y1 = x1[i] * inv * (1.0f + w[d]);
        float y2 = x2[i] * inv * (1.0f + w[d + 128]);
        dst[d]       = (y1 * c - y2 * sn) * scale;
        dst[d + 128] = (y2 * c + y1 * sn) * scale;
    }
}

// ---------------------------------------------------------------------------
// Sliding-window flash attention with tf32 mma.sync.
// BM=BN=64, D=256, 256 threads (8 warps = 4 row-groups x 2 col-halves).
//   scores: warp (wr,wc) computes m16 (rows 16wr..) x n32 (keys 32wc..)
//   PV:     warp (wr,wc) computes m16 x d128 (d-half wc), O accum 64 regs
// Q,K smem [row][d] pitch 260; V transposed [d][key] pitch 68; P [q][key] 68.
// ---------------------------------------------------------------------------
#define QP 260
#define VP 68
#define PP 68

__global__ __launch_bounds__(256, 1) void attn_mma_kernel()
{
    extern __shared__ float smf[];
    unsigned* Qs = (unsigned*)smf;           // [64][QP]
    unsigned* Ks = Qs + 64 * QP;             // [64][QP]
    unsigned* Vt = Ks + 64 * QP;             // [256][VP]
    float*    Ps = (float*)(Vt + 256 * VP);  // [64][PP]
    float*    ms = Ps + 64 * PP;             // [64]
    float*    ls = ms + 64;
    float*    cs = ls + 64;

    int qt = blockIdx.x, h = blockIdx.y, b = blockIdx.z;
    int q0 = qt * 64;
    int kh = h >> 1;

    const float* Qg = g_q + ((size_t)(b * NH + h) * NS + q0) * ND;
    const float* Kg = g_k + (size_t)(b * NKV + kh) * NS * ND;
    const float* Vg = g_v + (size_t)(b * NKV + kh) * NS * ND;

    int tid  = threadIdx.x;
    int lane = tid & 31;
    int warp = tid >> 5;
    int wr = warp & 3;
    int wc = warp >> 2;
    int fr = lane >> 2;
    int fc = lane & 3;

    // load Q tile as tf32
    for (int i = tid; i < 64 * 64; i += 256) {
        int r = i >> 6, c = (i & 63) << 2;
        float4 q4 = *(const float4*)(Qg + (size_t)r * ND + c);
        unsigned* d = Qs + r * QP + c;
        d[0] = f2tf32(q4.x); d[1] = f2tf32(q4.y);
        d[2] = f2tf32(q4.z); d[3] = f2tf32(q4.w);
    }
    if (tid < 64) { ms[tid] = -1e30f; ls[tid] = 0.0f; }

    float oacc[16][4];
#pragma unroll
    for (int t = 0; t < 16; t++)
#pragma unroll
        for (int e = 0; e < 4; e++) oacc[t][e] = 0.0f;

    int t0 = qt - 16; if (t0 < 0) t0 = 0;

    for (int kt = t0; kt <= qt; kt++) {
        int k0 = kt * 64;
        __syncthreads();

        // K tile (tf32, natural layout)
        for (int i = tid; i < 64 * 64; i += 256) {
            int r = i >> 6, c = (i & 63) << 2;
            float4 k4 = *(const float4*)(Kg + (size_t)(k0 + r) * ND + c);
            unsigned* d = Ks + r * QP + c;
            d[0] = f2tf32(k4.x); d[1] = f2tf32(k4.y);
            d[2] = f2tf32(k4.z); d[3] = f2tf32(k4.w);
        }
        // V tile transposed: warp handles 8 keys, lanes = 8 keys x 4 d-groups
        {
            int kk = (warp << 3) + (lane & 7);
            int dd = (lane >> 3) << 2;
            const float* vrow = Vg + (size_t)(k0 + kk) * ND;
#pragma unroll
            for (int c = 0; c < 256; c += 16) {
                float4 v4 = *(const float4*)(vrow + c + dd);
                unsigned* dst = Vt + (size_t)(c + dd) * VP + kk;
                dst[0]      = f2tf32(v4.x);
                dst[VP]     = f2tf32(v4.y);
                dst[2 * VP] = f2tf32(v4.z);
                dst[3 * VP] = f2tf32(v4.w);
            }
        }
        __syncthreads();

        // ---- scores: m16 x n32, k=256 ----
        float sacc[4][4];
#pragma unroll
        for (int t = 0; t < 4; t++)
#pragma unroll
            for (int e = 0; e < 4; e++) sacc[t][e] = 0.0f;

        int r0 = 16 * wr + fr;
#pragma unroll 4
        for (int kb = 0; kb < 256; kb += 8) {
            unsigned a0 = Qs[r0 * QP + kb + fc];
            unsigned a1 = Qs[(r0 + 8) * QP + kb + fc];
            unsigned a2 = Qs[r0 * QP + kb + fc + 4];
            unsigned a3 = Qs[(r0 + 8) * QP + kb + fc + 4];
#pragma unroll
            for (int nt = 0; nt < 4; nt++) {
                int n = 32 * wc + 8 * nt + fr;
                unsigned b0 = Ks[n * QP + kb + fc];
                unsigned b1 = Ks[n * QP + kb + fc + 4];
                mma_tf32(sacc[nt], a0, a1, a2, a3, b0, b1);
            }
        }

        // softcap + mask, write raw scores to Ps (float)
#pragma unroll
        for (int nt = 0; nt < 4; nt++) {
#pragma unroll
            for (int e = 0; e < 4; e++) {
                int r  = r0 + (e >> 1) * 8;
                int kj = k0 + 32 * wc + 8 * nt + 2 * fc + (e & 1);
                int qi = q0 + r;
                float v = tanhf(sacc[nt][e] * 0.02f) * 50.0f;
                bool ok = (kj <= qi) && (qi - kj < NWIN);
                sacc[nt][e] = ok ? v : -1e30f;
            }
            int col = 32 * wc + 8 * nt + 2 * fc;
            *(float2*)&Ps[r0 * PP + col]       = make_float2(sacc[nt][0], sacc[nt][1]);
            *(float2*)&Ps[(r0 + 8) * PP + col] = make_float2(sacc[nt][2], sacc[nt][3]);
        }
        __syncthreads();

        // ---- softmax: warp w owns rows 8w..8w+7; 4 lanes per row ----
        {
            int row = (warp << 3) + (lane >> 2);
            int cb  = lane & 3;
            float vbuf[16];
            float mx = -1e30f;
#pragma unroll
            for (int j = 0; j < 16; j++) {
                vbuf[j] = Ps[row * PP + cb + 4 * j];
                mx = fmaxf(mx, vbuf[j]);
            }
            mx = fmaxf(mx, __shfl_xor_sync(0xffffffffu, mx, 1));
            mx = fmaxf(mx, __shfl_xor_sync(0xffffffffu, mx, 2));
            float mold = ms[row];
            float mnew = fmaxf(mold, mx);
            float corr = __expf(mold - mnew);
            float rs = 0.0f;
#pragma unroll
            for (int j = 0; j < 16; j++) {
                float p = __expf(vbuf[j] - mnew);
                rs += p;
                Ps[row * PP + cb + 4 * j] = __uint_as_float(f2tf32(p));
            }
            rs += __shfl_xor_sync(0xffffffffu, rs, 1);
            rs += __shfl_xor_sync(0xffffffffu, rs, 2);
            if (cb == 0) {
                ms[row] = mnew;
                cs[row] = corr;
                ls[row] = ls[row] * corr + rs;
            }
        }
        __syncthreads();

        // ---- rescale O, then O += P @ V (m16 x d128, k=64) ----
        {
            float c0 = cs[r0], c1 = cs[r0 + 8];
#pragma unroll
            for (int nt = 0; nt < 16; nt++) {
                oacc[nt][0] *= c0; oacc[nt][1] *= c0;
                oacc[nt][2] *= c1; oacc[nt][3] *= c1;
            }
#pragma unroll
            for (int kc = 0; kc < 64; kc += 8) {
                unsigned a0 = __float_as_uint(Ps[r0 * PP + kc + fc]);
                unsigned a1 = __float_as_uint(Ps[(r0 + 8) * PP + kc + fc]);
                unsigned a2 = __float_as_uint(Ps[r0 * PP + kc + fc + 4]);
                unsigned a3 = __float_as_uint(Ps[(r0 + 8) * PP + kc + fc + 4]);
#pragma unroll
                for (int nt = 0; nt < 16; nt++) {
                    int dn = 128 * wc + 8 * nt + fr;
                    unsigned b0 = Vt[dn * VP + kc + fc];
                    unsigned b1 = Vt[dn * VP + kc + fc + 4];
                    mma_tf32(oacc[nt], a0, a1, a2, a3, b0, b1);
                }
            }
        }
    }

    // epilogue (ls written before last __syncthreads)
    {
        int r0 = 16 * wr + fr;
        float il0 = 1.0f / ls[r0];
        float il1 = 1.0f / ls[r0 + 8];
        float* Og = g_att + ((size_t)b * NS + q0) * (NH * ND) + h * ND;
#pragma unroll
        for (int nt = 0; nt < 16; nt++) {
            int col = 128 * wc + 8 * nt + 2 * fc;
            *(float2*)&Og[(size_t)r0 * (NH * ND) + col] =
                make_float2(oacc[nt][0] * il0, oacc[nt][1] * il0);
            *(float2*)&Og[(size_t)(r0 + 8) * (NH * ND) + col] =
                make_float2(oacc[nt][2] * il1, oacc[nt][3] * il1);
        }
    }
}

// ---------------------------------------------------------------------------
extern "C" void kernel_launch(void* const* d_in, const int* in_sizes, int n_in,
                              void* d_out, int out_size)
{
    const float* hidden = (const float*)d_in[0];
    const float* fcos   = (const float*)d_in[1];
    const float* fsin   = (const float*)d_in[2];
    const int*   kvidx  = (const int*)  d_in[3];
    const float* w_qkv  = (const float*)d_in[8];
    const float* w_o    = (const float*)d_in[9];
    const float* qnw    = (const float*)d_in[10];
    const float* knw    = (const float*)d_in[11];
    float* out = (float*)d_out;

    void* p;
    cudaGetSymbolAddress(&p, g_qkv); float* qkv_ptr = (float*)p;
    cudaGetSymbolAddress(&p, g_att); float* att_ptr = (float*)p;

    // 1) QKV projection (tf32 tensor cores)
    {
        dim3 grid((NH + 2 * NKV) * ND / 128, NB * NS / 128);
        tf32gemm_nt<<<grid, 256>>>(hidden, w_qkv, qkv_ptr,
                                   NB * NS, (NH + 2 * NKV) * ND, NE);
    }

    // 2) RMSNorm + RoPE + cache scatter
    norm_rope_kernel<<<NB * NS, 512>>>(fcos, fsin, kvidx, qnw, knw);

    // 3) sliding-window flash attention (tf32 tensor cores)
    {
        size_t smem = (size_t)(2 * 64 * QP + 256 * VP + 64 * PP + 192) * 4;
        cudaFuncSetAttribute(attn_mma_kernel,
                             cudaFuncAttributeMaxDynamicSharedMemorySize,
                             (int)smem);
        dim3 grid(NS / 64, NH, NB);
        attn_mma_kernel<<<grid, 256, smem>>>();
    }

    // 4) output projection (tf32 tensor cores)
    {
        dim3 grid(NE / 128, NB * NS / 128);
        tf32gemm_nt<<<grid, 256>>>(att_ptr, w_o, out, NB * NS, NE, NH * ND);
    }
}